// round 15
// baseline (speedup 1.0000x reference)
#include <cuda_runtime.h>
#include <cuda_fp16.h>
#include <math.h>

#define SS 32
#define EE 64
#define VV 32000
#define BB 4096
#define SB (SS*BB)

// packed-fp16 state. g_hf/g_hb words are PERMUTED (pcol) for direct k4f staging.
__device__ unsigned g_hf[(size_t)SB*32];
__device__ unsigned g_hb[(size_t)SB*32];
__device__ unsigned g_hL[BB*64];            // natural words (k5)
// packed-fp16 operands; k2f/k4f arrays word-PERMUTED (pairs words (w,w+4) adjacent)
__device__ unsigned r_emb[(size_t)VV*32];
__device__ unsigned r_Wif[256*32], r_Whf[256*32], r_Wib[256*32], r_Whb[256*32];
__device__ unsigned r_Wc[512*64];           // original rows, permuted words (k4f)
__device__ unsigned r_Whc[512*64];          // original rows, permuted words (k4f)
__device__ unsigned r_Wd[(size_t)VV*64];    // natural (k5)

__device__ __forceinline__ float atanh_(float x){
    float r; asm("tanh.approx.f32 %0, %1;" : "=f"(r) : "f"(x)); return r;
}
__device__ __forceinline__ float asigm(float x){ return 0.5f + 0.5f*atanh_(0.5f*x); }
__device__ __forceinline__ unsigned h2(float a, float b){
    __half2 hh = __floats2half2_rn(a, b);
    return *reinterpret_cast<unsigned*>(&hh);
}
__device__ __forceinline__ int pcol(int c){
    int o = c&7; return (c&~7) + ((o<4)? o*2 : (o-4)*2+1);
}
__device__ __forceinline__ unsigned sptr(const void* p){
    return (unsigned)__cvta_generic_to_shared(p);
}
__device__ __forceinline__ void cpa16(unsigned d, const void* s){
    asm volatile("cp.async.cg.shared.global [%0], [%1], 16;" :: "r"(d), "l"(s));
}
#define CPCOMMIT() asm volatile("cp.async.commit_group;")
#define CPWAIT(n)  asm volatile("cp.async.wait_group %0;" :: "n"(n))
#define CLSYNC() do { \
    asm volatile("barrier.cluster.arrive.aligned;" ::: "memory"); \
    asm volatile("barrier.cluster.wait.aligned;"   ::: "memory"); } while(0)

__device__ __forceinline__ void mma16(float* c, const unsigned* a, const unsigned* b){
    asm volatile("mma.sync.aligned.m16n8k16.row.col.f32.f16.f16.f32 "
        "{%0,%1,%2,%3}, {%4,%5,%6,%7}, {%8,%9}, {%0,%1,%2,%3};"
        : "+f"(c[0]), "+f"(c[1]), "+f"(c[2]), "+f"(c[3])
        : "r"(a[0]), "r"(a[1]), "r"(a[2]), "r"(a[3]), "r"(b[0]), "r"(b[1]));
}
__device__ __forceinline__ void ldA64(unsigned* a, const unsigned* S, int r0,
                                      int K, int woff){
    uint2 v0 = *(const uint2*)&S[r0*K + woff];
    uint2 v1 = *(const uint2*)&S[(r0+8)*K + woff];
    a[0]=v0.x; a[1]=v1.x; a[2]=v0.y; a[3]=v1.y;
}
__device__ __forceinline__ void ldA(unsigned* a, const unsigned* S, int m0, int k0,
                                    int pad, int gid, int tig){
    a[0] = S[(m0+gid  )*pad + k0+tig  ];
    a[1] = S[(m0+gid+8)*pad + k0+tig  ];
    a[2] = S[(m0+gid  )*pad + k0+tig+4];
    a[3] = S[(m0+gid+8)*pad + k0+tig+4];
}
__device__ __forceinline__ void ldB(unsigned* b, const unsigned* S, int n0, int k0,
                                    int pad, int gid, int tig){
    b[0] = S[(n0+gid)*pad + k0+tig  ];
    b[1] = S[(n0+gid)*pad + k0+tig+4];
}
__device__ __forceinline__ void stcs2(float* p, float x, float y){
    asm volatile("st.global.cs.v2.f32 [%0], {%1,%2};" :: "l"(p), "f"(x), "f"(y) : "memory");
}

// ======== K0: convert all operands to packed fp16 (permute where needed) ========
__global__ void k0(const float* __restrict__ emb,
    const float* __restrict__ Wif, const float* __restrict__ Whf,
    const float* __restrict__ Wib, const float* __restrict__ Whb,
    const float* __restrict__ Wc,  const float* __restrict__ Whc,
    const float* __restrict__ Wd)
{
    int tid = blockIdx.x*256 + threadIdx.x, nt = gridDim.x*256;
    for (int i = tid; i < VV*32; i += nt) {
        int v = i>>5, p = i&31;
        r_emb[v*32 + pcol(p)] = h2(emb[v*64+2*p], emb[v*64+2*p+1]);
    }
    for (int i = tid; i < 256*32; i += nt) {
        int n = i>>5, p = i&31, d = n*32 + pcol(p);
        r_Wif[d] = h2(Wif[n*64+2*p], Wif[n*64+2*p+1]);
        r_Whf[d] = h2(Whf[n*64+2*p], Whf[n*64+2*p+1]);
        r_Wib[d] = h2(Wib[n*64+2*p], Wib[n*64+2*p+1]);
        r_Whb[d] = h2(Whb[n*64+2*p], Whb[n*64+2*p+1]);
    }
    for (int i = tid; i < 512*64; i += nt) {
        int n = i>>6, p = i&63, d = n*64 + pcol(p);
        r_Wc[d]  = h2(Wc[n*128+2*p],  Wc[n*128+2*p+1]);
        r_Whc[d] = h2(Whc[n*128+2*p], Whc[n*128+2*p+1]);
    }
    for (int i = tid; i < VV*64; i += nt) {
        int n = i>>6, p = i&63;
        r_Wd[n*64 + p] = h2(Wd[(size_t)n*128+2*p], Wd[(size_t)n*128+2*p+1]);
    }
}

// ======== K2F: fused embed+gates+recurrence. 64 rows/CTA, 1024 thr, grid 128 ====
__global__ __launch_bounds__(1024) void k2f(const void* __restrict__ xraw,
    const float* __restrict__ bif, const float* __restrict__ bhf,
    const float* __restrict__ h0f, const float* __restrict__ c0f,
    const float* __restrict__ bib, const float* __restrict__ bhb,
    const float* __restrict__ h0b, const float* __restrict__ c0b)
{
    extern __shared__ unsigned sm[];
    unsigned* Wi = sm;              // [256][32] perm+swz
    unsigned* Wh = sm + 8192;       // [256][32]
    unsigned* As = sm + 16384;      // 2 x [64][32]
    unsigned* Hs = sm + 20480;      // 2 x [64][32]
    int*      Tk = (int*)(sm + 24576);
    __shared__ int s64;
    const int tx = threadIdx.x, dir = blockIdx.y, b0 = blockIdx.x*64;
    const unsigned* Wih = dir ? r_Wib : r_Wif;
    const unsigned* Whh = dir ? r_Whb : r_Whf;
    const float* bi  = dir ? bib : bif;
    const float* bh  = dir ? bhb : bhf;
    const float* h0  = dir ? h0b : h0f;
    const float* c0  = dir ? c0b : c0f;
    unsigned* H = dir ? g_hb : g_hf;

    for (int idx = tx; idx < 256*8; idx += 1024) {
        int n = idx>>3, c4 = idx&7;
        int dst = n*32 + ((c4*4) ^ ((n&3)<<3));
        cpa16(sptr(&Wi[dst]), &Wih[n*32 + c4*4]);
        cpa16(sptr(&Wh[dst]), &Whh[n*32 + c4*4]);
    }
    CPCOMMIT();
    if (tx == 0) {
        const int* p = (const int*)xraw; int f = 1;
        for (int q = 0; q < 64; q++) if (p[2*q+1] != 0) { f = 0; break; }
        s64 = f;
    }
    __syncthreads();
    {
        const long long* x64 = (const long long*)xraw;
        const int* x32 = (const int*)xraw;
        const int is64 = s64;
        for (int idx = tx; idx < 2048; idx += 1024) {
            int t = idx>>6, r = idx&63;
            int pos = dir ? (SS-1-t)*BB + b0 + r : t*BB + b0 + r;
            Tk[idx] = is64 ? (int)x64[pos] : x32[pos];
        }
    }
    for (int idx = tx; idx < 64*32; idx += 1024) {
        int r = idx>>5, p = idx&31;
        Hs[r*32 + (pcol(p) ^ ((r&3)<<3))] =
            h2(h0[(b0+r)*64+2*p], h0[(b0+r)*64+2*p+1]);
    }
    __syncthreads();
    for (int idx = tx; idx < 64*8; idx += 1024) {
        int r = idx>>3, c4 = idx&7;
        cpa16(sptr(&As[r*32 + ((c4*4) ^ ((r&3)<<3))]), &r_emb[Tk[r]*32 + c4*4]);
    }
    CPCOMMIT();

    const int lid = tx&31, wid = tx>>5, gid = lid>>2, tig = lid&3;
    const int wm = wid>>3, wn = wid&7;
    const int m0 = wm*16;
    const int jc = wn*8 + tig*2;
    const int sw = (gid&3)<<3;
    float bA[4][2];
    #pragma unroll
    for (int g = 0; g < 4; g++) {
        bA[g][0] = bi[g*64+jc]   + bh[g*64+jc];
        bA[g][1] = bi[g*64+jc+1] + bh[g*64+jc+1];
    }
    float creg[4];
    {
        float2 c1 = *(const float2*)&c0[(b0+m0+gid)*64 + jc];
        float2 c2 = *(const float2*)&c0[(b0+m0+gid+8)*64 + jc];
        creg[0]=c1.x; creg[1]=c1.y; creg[2]=c2.x; creg[3]=c2.y;
    }
    const int pj = pcol(jc>>1) ^ sw;       // smem word (perm+swz)
    const int pnp = pcol(jc>>1);           // global H word (PERMUTED for k4f)
    for (int t = 0; t < SS; t++) {
        if (t < SS-1) {
            for (int idx = tx; idx < 64*8; idx += 1024) {
                int r = idx>>3, c4 = idx&7;
                cpa16(sptr(&As[((t+1)&1)*2048 + r*32 + ((c4*4) ^ ((r&3)<<3))]),
                      &r_emb[Tk[(t+1)*64+r]*32 + c4*4]);
            }
            CPCOMMIT(); CPWAIT(1);
        } else CPWAIT(0);
        __syncthreads();
        const unsigned* Ab = As + (t&1)*2048;
        const unsigned* Hb = Hs + (t&1)*2048;
        unsigned* Hw = Hs + ((t+1)&1)*2048;
        float acc[4][4];
        #pragma unroll
        for (int g = 0; g < 4; g++) {
            acc[g][0]=bA[g][0]; acc[g][1]=bA[g][1];
            acc[g][2]=bA[g][0]; acc[g][3]=bA[g][1];
        }
        #pragma unroll
        for (int kg = 0; kg < 4; kg++) {
            const int woff = ((kg*4 + tig)<<1) ^ sw;
            unsigned a[4], bf[4][2];
            ldA64(a, Ab, m0+gid, 32, woff);
            #pragma unroll
            for (int g = 0; g < 4; g++) {
                uint2 w = *(const uint2*)&Wi[(g*64 + wn*8 + gid)*32 + woff];
                bf[g][0]=w.x; bf[g][1]=w.y;
            }
            #pragma unroll
            for (int g = 0; g < 4; g++) mma16(acc[g], a, bf[g]);
        }
        #pragma unroll
        for (int kg = 0; kg < 4; kg++) {
            const int woff = ((kg*4 + tig)<<1) ^ sw;
            unsigned a[4], bf[4][2];
            ldA64(a, Hb, m0+gid, 32, woff);
            #pragma unroll
            for (int g = 0; g < 4; g++) {
                uint2 w = *(const uint2*)&Wh[(g*64 + wn*8 + gid)*32 + woff];
                bf[g][0]=w.x; bf[g][1]=w.y;
            }
            #pragma unroll
            for (int g = 0; g < 4; g++) mma16(acc[g], a, bf[g]);
        }
        {
            float hv[4];
            #pragma unroll
            for (int q = 0; q < 4; q++) {
                float iv = asigm(acc[0][q]);
                float fv = asigm(acc[1][q]);
                float gv = atanh_(acc[2][q]);
                float ov = asigm(acc[3][q]);
                float c = fv*creg[q] + iv*gv;
                hv[q] = ov*atanh_(c);
                creg[q] = c;
            }
            unsigned p1 = h2(hv[0], hv[1]);
            unsigned p2 = h2(hv[2], hv[3]);
            int r1 = m0 + gid, r2 = r1 + 8;
            Hw[r1*32 + pj] = p1;
            Hw[r2*32 + pj] = p2;
            H[(size_t)(t*BB + b0 + r1)*32 + pnp] = p1;
            H[(size_t)(t*BB + b0 + r2)*32 + pnp] = p2;
        }
    }
}

// ======== K4F: FUSED combiner (input GEMM + recurrence), 2-CTA cluster ========
// Per pair: 64 batch rows; CTA owns hidden dims [rank*64,+64) for all 4 gates.
// Local gate-col n = wcol*16+nb*8+tig*2+e <-> (gate=nb*2+e, dim=wcol*4+tig).
__global__ __launch_bounds__(1024) __cluster_dims__(2,1,1) void k4f(
    const float* __restrict__ h0c, const float* __restrict__ c0c,
    const float* __restrict__ bic, const float* __restrict__ bhc)
{
    extern __shared__ unsigned sm[];
    unsigned* Wcs = sm;             // [256][64] Wih_c local, remapped+perm+swz
    unsigned* Ws  = sm + 16384;     // [256][64] Whh_c local
    unsigned* Hs  = sm + 32768;     // 2 x [64][64]
    unsigned* Xs  = sm + 40960;     // 2 x [64][64]  ([hf|hb] per step)
    const int tx = threadIdx.x;
    unsigned rank; asm("mov.u32 %0, %%cluster_ctarank;" : "=r"(rank));
    const int b0 = (blockIdx.x >> 1) * 64;

    for (int idx = tx; idx < 256*16; idx += 1024) {
        int n = idx>>4, c4 = idx&15;
        int g = ((n>>3)&1)*2 + (n&1);
        int d = (n>>4)*4 + ((n>>1)&3);
        int src = (g*128 + (int)rank*64 + d)*64 + c4*4;
        int dst = n*64 + ((c4*4) ^ ((n&3)<<3));
        cpa16(sptr(&Wcs[dst]), &r_Wc[src]);
        cpa16(sptr(&Ws[dst]),  &r_Whc[src]);
    }
    // Xs[0]: t=0 step input [hf|hb] (already permuted words in global)
    for (int idx = tx; idx < 64*16; idx += 1024) {
        int r = idx>>4, c4 = idx&15;
        int dst = r*64 + ((c4*4) ^ ((r&3)<<3));
        const unsigned* src = (c4 < 8) ? &g_hf[(size_t)(b0+r)*32 + c4*4]
                                       : &g_hb[(size_t)(b0+r)*32 + (c4-8)*4];
        cpa16(sptr(&Xs[dst]), src);
    }
    CPCOMMIT();
    for (int idx = tx; idx < 64*64; idx += 1024) {
        int r = idx>>6, p = idx&63;
        Hs[r*64 + (pcol(p) ^ ((r&3)<<3))] =
            h2(h0c[(b0+r)*128+2*p], h0c[(b0+r)*128+2*p+1]);
    }

    const int lid = tx&31, wid = tx>>5, gid = lid>>2, tig = lid&3;
    const int wm2 = wid>>4;
    const int wcol = wid&15;
    const int n0 = wcol*16;
    const int sw = (gid&3)<<3;
    const int dloc = wcol*4 + tig;
    const int gd = (int)rank*64 + dloc;
    const int pw = pcol(gd>>1) ^ sw;
    unsigned peerHs;
    asm("mapa.shared::cluster.u32 %0, %1, %2;"
        : "=r"(peerHs) : "r"(sptr(Hs)), "r"(rank^1u));

    float bias[2][2];
    #pragma unroll
    for (int nb = 0; nb < 2; nb++) {
        bias[nb][0] = bic[(nb*2  )*128 + gd] + bhc[(nb*2  )*128 + gd];
        bias[nb][1] = bic[(nb*2+1)*128 + gd] + bhc[(nb*2+1)*128 + gd];
    }
    float creg[2][2];
    #pragma unroll
    for (int mb = 0; mb < 2; mb++) {
        creg[mb][0] = c0c[(b0+wm2*32+mb*16+gid)*128 + gd];
        creg[mb][1] = c0c[(b0+wm2*32+mb*16+gid+8)*128 + gd];
    }
    CPWAIT(0);
    __syncthreads();

    #pragma unroll 1
    for (int t = 0; t < SS; t++) {
        if (t < SS-1) {     // prefetch Xs[t+1]
            for (int idx = tx; idx < 64*16; idx += 1024) {
                int r = idx>>4, c4 = idx&15;
                int dst = ((t+1)&1)*4096 + r*64 + ((c4*4) ^ ((r&3)<<3));
                const unsigned* src = (c4 < 8)
                    ? &g_hf[(size_t)((t+1)*BB+b0+r)*32 + c4*4]
                    : &g_hb[(size_t)((t+1)*BB+b0+r)*32 + (c4-8)*4];
                cpa16(sptr(&Xs[dst]), src);
            }
            CPCOMMIT(); CPWAIT(1);
        } else CPWAIT(0);
        __syncthreads();
        const unsigned* Xb = Xs + (t&1)*4096;
        const unsigned* Hb = Hs + (t&1)*4096;
        unsigned* Hw = Hs + ((t+1)&1)*4096;
        const unsigned pbuf = ((unsigned)((t+1)&1))*16384u;
        float acc[2][2][4];
        #pragma unroll
        for (int mb = 0; mb < 2; mb++)
            #pragma unroll
            for (int nb = 0; nb < 2; nb++) {
                acc[mb][nb][0]=bias[nb][0]; acc[mb][nb][1]=bias[nb][1];
                acc[mb][nb][2]=bias[nb][0]; acc[mb][nb][3]=bias[nb][1];
            }
        #pragma unroll
        for (int kg = 0; kg < 8; kg++) {        // input GEMM: X @ Wc^T
            const int woff = ((kg*4 + tig)<<1) ^ sw;
            unsigned a[2][4], bf[2][2];
            #pragma unroll
            for (int mb = 0; mb < 2; mb++) ldA64(a[mb], Xb, wm2*32+mb*16+gid, 64, woff);
            #pragma unroll
            for (int nb = 0; nb < 2; nb++) {
                uint2 w = *(const uint2*)&Wcs[(n0 + nb*8 + gid)*64 + woff];
                bf[nb][0]=w.x; bf[nb][1]=w.y;
            }
            #pragma unroll
            for (int mb = 0; mb < 2; mb++)
                #pragma unroll
                for (int nb = 0; nb < 2; nb++) mma16(acc[mb][nb], a[mb], bf[nb]);
        }
        #pragma unroll
        for (int kg = 0; kg < 8; kg++) {        // recurrence: H @ Whc^T
            const int woff = ((kg*4 + tig)<<1) ^ sw;
            unsigned a[2][4], bf[2][2];
            #pragma unroll
            for (int mb = 0; mb < 2; mb++) ldA64(a[mb], Hb, wm2*32+mb*16+gid, 64, woff);
            #pragma unroll
            for (int nb = 0; nb < 2; nb++) {
                uint2 w = *(const uint2*)&Ws[(n0 + nb*8 + gid)*64 + woff];
                bf[nb][0]=w.x; bf[nb][1]=w.y;
            }
            #pragma unroll
            for (int mb = 0; mb < 2; mb++)
                #pragma unroll
                for (int nb = 0; nb < 2; nb++) mma16(acc[mb][nb], a[mb], bf[nb]);
        }
        #pragma unroll
        for (int mb = 0; mb < 2; mb++) {
            float iv0 = asigm (acc[mb][0][0]);
            float fv0 = asigm (acc[mb][0][1]);
            float gv0 = atanh_(acc[mb][1][0]);
            float ov0 = asigm (acc[mb][1][1]);
            float iv1 = asigm (acc[mb][0][2]);
            float fv1 = asigm (acc[mb][0][3]);
            float gv1 = atanh_(acc[mb][1][2]);
            float ov1 = asigm (acc[mb][1][3]);
            float cn0 = fv0*creg[mb][0] + iv0*gv0;
            float cn1 = fv1*creg[mb][1] + iv1*gv1;
            creg[mb][0]=cn0; creg[mb][1]=cn1;
            float hv0 = ov0*atanh_(cn0);
            float hv1 = ov1*atanh_(cn1);
            float pp0 = __shfl_xor_sync(0xffffffffu, hv0, 1);
            float pp1 = __shfl_xor_sync(0xffffffffu, hv1, 1);
            if ((tig & 1) == 0) {
                unsigned w0v = h2(hv0, pp0);
                unsigned w1v = h2(hv1, pp1);
                int r0 = wm2*32 + mb*16 + gid, r1 = r0 + 8;
                if (t < SS-1) {
                    Hw[r0*64 + pw] = w0v;
                    Hw[r1*64 + pw] = w1v;
                    asm volatile("st.shared::cluster.b32 [%0], %1;"
                        :: "r"(peerHs + pbuf + (unsigned)(r0*64+pw)*4u), "r"(w0v) : "memory");
                    asm volatile("st.shared::cluster.b32 [%0], %1;"
                        :: "r"(peerHs + pbuf + (unsigned)(r1*64+pw)*4u), "r"(w1v) : "memory");
                } else {
                    g_hL[(b0+r0)*64 + (gd>>1)] = w0v;
                    g_hL[(b0+r1)*64 + (gd>>1)] = w1v;
                }
            }
        }
        CLSYNC();
    }
}

// ======== K5: out = hL @ Wd^T + bd. Wd-resident fp16, stream hL 8 m-tiles ====
__global__ __launch_bounds__(256,2) void k5(
    const float* __restrict__ bd, float* __restrict__ out)
{
    extern __shared__ unsigned sm[];
    unsigned* Bs = sm;            // [128][68]
    unsigned* Ab = sm + 8704;     // 2 x [128][20]
    const int tx = threadIdx.x;
    const int v0 = blockIdx.x*128;
    const int mbase = blockIdx.y*1024;
    for (int idx = tx; idx < 128*16; idx += 256) {
        int n = idx>>4, c4 = idx&15;
        cpa16(sptr(&Bs[n*68 + c4*4]), &r_Wd[(size_t)(v0+n)*64 + c4*4]);
    }
    for (int idx = tx; idx < 512; idx += 256) {
        int r = idx>>2, c4 = idx&3;
        cpa16(sptr(&Ab[r*20 + c4*4]), &g_hL[(mbase+r)*64 + c4*4]);
    }
    CPCOMMIT();
    const int lid = tx&31, wid = tx>>5, gid = lid>>2, tig = lid&3;
    const int wm = wid&1, wn = wid>>1;
    #pragma unroll 1
    for (int mt = 0; mt < 8; mt++) {
        float acc[4][4][4];
        #pragma unroll
        for (int mb = 0; mb < 4; mb++)
            #pragma unroll
            for (int nb = 0; nb < 4; nb++)
                #pragma unroll
                for (int r = 0; r < 4; r++) acc[mb][nb][r] = 0.f;
        #pragma unroll 1
        for (int c = 0; c < 4; c++) {
            CPWAIT(0); __syncthreads();
            int i = mt*4 + c;
            if (i < 31) {
                int nm = (i+1)>>2, nc = (i+1)&3, buf = (i+1)&1;
                for (int idx = tx; idx < 512; idx += 256) {
                    int r = idx>>2, c4 = idx&3;
                    cpa16(sptr(&Ab[buf*2560 + r*20 + c4*4]),
                          &g_hL[(mbase + nm*128 + r)*64 + nc*16 + c4*4]);
                }
                CPCOMMIT();
            }
            const unsigned* Au = Ab + (i&1)*2560;
            #pragma unroll
            for (int kg = 0; kg < 2; kg++) {
                unsigned a[4][4], b[4][2];
                #pragma unroll
                for (int mb = 0; mb < 4; mb++) ldA(a[mb], Au, wm*64+mb*16, kg*8, 20, gid, tig);
                #pragma unroll
                for (int nb = 0; nb < 4; nb++) ldB(b[nb], Bs, wn*32+nb*8, c*16+kg*8, 68, gid, tig);
                #pragma unroll
                for (int mb = 0; mb < 4; mb++)
                    #pragma unroll
                    for (int nb = 0; nb < 4; nb++) mma16(acc[mb][nb], a[mb], b[nb]);
            }
        }
        #pragma unroll
        for (int mb = 0; mb < 4; mb++)
            #pragma unroll
            for (int nb = 0; nb < 4; nb++) {
                int row = mbase + mt*128 + wm*64 + mb*16 + gid;
                int col = v0 + wn*32 + nb*8 + tig*2;
                float2 bb = *(const float2*)&bd[col];
                stcs2(&out[(size_t)row*VV + col],     acc[mb][nb][0]+bb.x, acc[mb][nb][1]+bb.y);
                stcs2(&out[(size_t)(row+8)*VV + col], acc[mb][nb][2]+bb.x, acc[mb][nb][3]+bb.y);
            }
    }
}

extern "C" void kernel_launch(void* const* d_in, const int* in_sizes, int n_in,
                              void* d_out, int out_size) {
    const void*  x     = d_in[0];
    const float* h0f   = (const float*)d_in[1];
    const float* c0f   = (const float*)d_in[2];
    const float* h0b   = (const float*)d_in[3];
    const float* c0b   = (const float*)d_in[4];
    const float* h0c   = (const float*)d_in[5];
    const float* c0c   = (const float*)d_in[6];
    const float* emb   = (const float*)d_in[7];
    const float* Wih_f = (const float*)d_in[8];
    const float* Whh_f = (const float*)d_in[9];
    const float* bih_f = (const float*)d_in[10];
    const float* bhh_f = (const float*)d_in[11];
    const float* Wih_b = (const float*)d_in[12];
    const float* Whh_b = (const float*)d_in[13];
    const float* bih_b = (const float*)d_in[14];
    const float* bhh_b = (const float*)d_in[15];
    const float* Wih_c = (const float*)d_in[16];
    const float* Whh_c = (const float*)d_in[17];
    const float* bih_c = (const float*)d_in[18];
    const float* bhh_c = (const float*)d_in[19];
    const float* Wd    = (const float*)d_in[20];
    const float* bd    = (const float*)d_in[21];
    float* out = (float*)d_out;

    const int s2  = (24576 + 2048)*4;      // 106496
    const int s4  = 49152*4;               // 196608 (Wcs+Ws+Hs+Xs)
    const int s5  = (8704 + 2*2560)*4;     // 55296
    cudaFuncSetAttribute(k2f, cudaFuncAttributeMaxDynamicSharedMemorySize, s2);
    cudaFuncSetAttribute(k4f, cudaFuncAttributeMaxDynamicSharedMemorySize, s4);
    cudaFuncSetAttribute(k5,  cudaFuncAttributeMaxDynamicSharedMemorySize, s5);

    k0<<<1024, 256>>>(emb, Wih_f, Whh_f, Wih_b, Whh_b, Wih_c, Whh_c, Wd);
    k2f<<<dim3(BB/64, 2), 1024, s2>>>(x, bih_f, bhh_f, h0f, c0f, bih_b, bhh_b, h0b, c0b);
    k4f<<<128, 1024, s4>>>(h0c, c0c, bih_c, bhh_c);
    k5<<<dim3(VV/128, 4), 256, s5>>>(bd, out);
}

// round 16
// speedup vs baseline: 1.2839x; 1.2839x over previous
#include <cuda_runtime.h>
#include <cuda_fp16.h>
#include <math.h>

#define SS 32
#define EE 64
#define VV 32000
#define BB 4096
#define SB (SS*BB)

// packed-fp16 state (word p holds elements 2p,2p+1); g_hL words PERMUTED (pcol)
__device__ unsigned g_hf[(size_t)SB*32];
__device__ unsigned g_hb[(size_t)SB*32];
__device__ float    g_Gc[(size_t)SB*512];   // fp32, GATE-INTERLEAVED cols c = 4*dim+gate
__device__ unsigned g_hL[BB*64];
// packed-fp16 operands; k2f/k4c/k5 arrays word-PERMUTED (pairs (w,w+4) adjacent)
__device__ unsigned r_emb[(size_t)VV*32];
__device__ unsigned r_Wif[256*32], r_Whf[256*32], r_Wib[256*32], r_Whb[256*32];
__device__ unsigned r_Wc[512*64];           // interleaved rows c=4d+g, natural words (k3)
__device__ unsigned r_Whc[512*64];          // original rows, permuted words (k4c)
__device__ unsigned r_Wd[(size_t)VV*64];    // permuted words (k5)

__device__ __forceinline__ float atanh_(float x){
    float r; asm("tanh.approx.f32 %0, %1;" : "=f"(r) : "f"(x)); return r;
}
__device__ __forceinline__ float asigm(float x){ return 0.5f + 0.5f*atanh_(0.5f*x); }
__device__ __forceinline__ unsigned h2(float a, float b){
    __half2 hh = __floats2half2_rn(a, b);
    return *reinterpret_cast<unsigned*>(&hh);
}
__device__ __forceinline__ int pcol(int c){
    int o = c&7; return (c&~7) + ((o<4)? o*2 : (o-4)*2+1);
}
__device__ __forceinline__ unsigned sptr(const void* p){
    return (unsigned)__cvta_generic_to_shared(p);
}
__device__ __forceinline__ void cpa16(unsigned d, const void* s){
    asm volatile("cp.async.cg.shared.global [%0], [%1], 16;" :: "r"(d), "l"(s));
}
#define CPCOMMIT() asm volatile("cp.async.commit_group;")
#define CPWAIT(n)  asm volatile("cp.async.wait_group %0;" :: "n"(n))
#define CLSYNC() do { \
    asm volatile("barrier.cluster.arrive.aligned;" ::: "memory"); \
    asm volatile("barrier.cluster.wait.aligned;"   ::: "memory"); } while(0)

__device__ __forceinline__ void mma16(float* c, const unsigned* a, const unsigned* b){
    asm volatile("mma.sync.aligned.m16n8k16.row.col.f32.f16.f16.f32 "
        "{%0,%1,%2,%3}, {%4,%5,%6,%7}, {%8,%9}, {%0,%1,%2,%3};"
        : "+f"(c[0]), "+f"(c[1]), "+f"(c[2]), "+f"(c[3])
        : "r"(a[0]), "r"(a[1]), "r"(a[2]), "r"(a[3]), "r"(b[0]), "r"(b[1]));
}
__device__ __forceinline__ void ldA64(unsigned* a, const unsigned* S, int r0,
                                      int K, int woff){
    uint2 v0 = *(const uint2*)&S[r0*K + woff];
    uint2 v1 = *(const uint2*)&S[(r0+8)*K + woff];
    a[0]=v0.x; a[1]=v1.x; a[2]=v0.y; a[3]=v1.y;
}
__device__ __forceinline__ void ldA(unsigned* a, const unsigned* S, int m0, int k0,
                                    int pad, int gid, int tig){
    a[0] = S[(m0+gid  )*pad + k0+tig  ];
    a[1] = S[(m0+gid+8)*pad + k0+tig  ];
    a[2] = S[(m0+gid  )*pad + k0+tig+4];
    a[3] = S[(m0+gid+8)*pad + k0+tig+4];
}
__device__ __forceinline__ void ldB(unsigned* b, const unsigned* S, int n0, int k0,
                                    int pad, int gid, int tig){
    b[0] = S[(n0+gid)*pad + k0+tig  ];
    b[1] = S[(n0+gid)*pad + k0+tig+4];
}
__device__ __forceinline__ void stcs2(float* p, float x, float y){
    asm volatile("st.global.cs.v2.f32 [%0], {%1,%2};" :: "l"(p), "f"(x), "f"(y) : "memory");
}

// ======== K0 ========
__global__ void k0(const float* __restrict__ emb,
    const float* __restrict__ Wif, const float* __restrict__ Whf,
    const float* __restrict__ Wib, const float* __restrict__ Whb,
    const float* __restrict__ Wc,  const float* __restrict__ Whc,
    const float* __restrict__ Wd)
{
    int tid = blockIdx.x*256 + threadIdx.x, nt = gridDim.x*256;
    for (int i = tid; i < VV*32; i += nt) {
        int v = i>>5, p = i&31;
        r_emb[v*32 + pcol(p)] = h2(emb[v*64+2*p], emb[v*64+2*p+1]);
    }
    for (int i = tid; i < 256*32; i += nt) {
        int n = i>>5, p = i&31, d = n*32 + pcol(p);
        r_Wif[d] = h2(Wif[n*64+2*p], Wif[n*64+2*p+1]);
        r_Whf[d] = h2(Whf[n*64+2*p], Whf[n*64+2*p+1]);
        r_Wib[d] = h2(Wib[n*64+2*p], Wib[n*64+2*p+1]);
        r_Whb[d] = h2(Whb[n*64+2*p], Whb[n*64+2*p+1]);
    }
    for (int i = tid; i < 512*64; i += nt) {
        int n = i>>6, p = i&63;
        int g = n>>7, dd = n&127;
        r_Wc[(dd*4+g)*64 + p] = h2(Wc[n*128+2*p], Wc[n*128+2*p+1]);     // k3
        r_Whc[n*64 + pcol(p)] = h2(Whc[n*128+2*p], Whc[n*128+2*p+1]);   // k4c
    }
    for (int i = tid; i < VV*64; i += nt) {
        int n = i>>6, p = i&63;
        r_Wd[n*64 + pcol(p)] = h2(Wd[(size_t)n*128+2*p], Wd[(size_t)n*128+2*p+1]);
    }
}

// ======== K2F: fused embed+gates+recurrence. 64 rows/CTA, 1024 thr, grid 128 ====
__global__ __launch_bounds__(1024) void k2f(const void* __restrict__ xraw,
    const float* __restrict__ bif, const float* __restrict__ bhf,
    const float* __restrict__ h0f, const float* __restrict__ c0f,
    const float* __restrict__ bib, const float* __restrict__ bhb,
    const float* __restrict__ h0b, const float* __restrict__ c0b)
{
    extern __shared__ unsigned sm[];
    unsigned* Wi = sm;              // [256][32] perm+swz
    unsigned* Wh = sm + 8192;       // [256][32]
    unsigned* As = sm + 16384;      // 2 x [64][32]
    unsigned* Hs = sm + 20480;      // 2 x [64][32]
    int*      Tk = (int*)(sm + 24576);
    __shared__ int s64;
    const int tx = threadIdx.x, dir = blockIdx.y, b0 = blockIdx.x*64;
    const unsigned* Wih = dir ? r_Wib : r_Wif;
    const unsigned* Whh = dir ? r_Whb : r_Whf;
    const float* bi  = dir ? bib : bif;
    const float* bh  = dir ? bhb : bhf;
    const float* h0  = dir ? h0b : h0f;
    const float* c0  = dir ? c0b : c0f;
    unsigned* H = dir ? g_hb : g_hf;

    for (int idx = tx; idx < 256*8; idx += 1024) {
        int n = idx>>3, c4 = idx&7;
        int dst = n*32 + ((c4*4) ^ ((n&3)<<3));
        cpa16(sptr(&Wi[dst]), &Wih[n*32 + c4*4]);
        cpa16(sptr(&Wh[dst]), &Whh[n*32 + c4*4]);
    }
    CPCOMMIT();
    if (tx == 0) {
        const int* p = (const int*)xraw; int f = 1;
        for (int q = 0; q < 64; q++) if (p[2*q+1] != 0) { f = 0; break; }
        s64 = f;
    }
    __syncthreads();
    {
        const long long* x64 = (const long long*)xraw;
        const int* x32 = (const int*)xraw;
        const int is64 = s64;
        for (int idx = tx; idx < 2048; idx += 1024) {
            int t = idx>>6, r = idx&63;
            int pos = dir ? (SS-1-t)*BB + b0 + r : t*BB + b0 + r;
            Tk[idx] = is64 ? (int)x64[pos] : x32[pos];
        }
    }
    for (int idx = tx; idx < 64*32; idx += 1024) {
        int r = idx>>5, p = idx&31;
        Hs[r*32 + (pcol(p) ^ ((r&3)<<3))] =
            h2(h0[(b0+r)*64+2*p], h0[(b0+r)*64+2*p+1]);
    }
    __syncthreads();
    for (int idx = tx; idx < 64*8; idx += 1024) {
        int r = idx>>3, c4 = idx&7;
        cpa16(sptr(&As[r*32 + ((c4*4) ^ ((r&3)<<3))]), &r_emb[Tk[r]*32 + c4*4]);
    }
    CPCOMMIT();

    const int lid = tx&31, wid = tx>>5, gid = lid>>2, tig = lid&3;
    const int wm = wid>>3, wn = wid&7;
    const int m0 = wm*16;
    const int jc = wn*8 + tig*2;
    const int sw = (gid&3)<<3;
    float bA[4][2];
    #pragma unroll
    for (int g = 0; g < 4; g++) {
        bA[g][0] = bi[g*64+jc]   + bh[g*64+jc];
        bA[g][1] = bi[g*64+jc+1] + bh[g*64+jc+1];
    }
    float creg[4];
    {
        float2 c1 = *(const float2*)&c0[(b0+m0+gid)*64 + jc];
        float2 c2 = *(const float2*)&c0[(b0+m0+gid+8)*64 + jc];
        creg[0]=c1.x; creg[1]=c1.y; creg[2]=c2.x; creg[3]=c2.y;
    }
    const int pj = pcol(jc>>1) ^ sw;
    const int pn = jc>>1;                 // natural word for g_hf/g_hb (k3 reads natural)
    for (int t = 0; t < SS; t++) {
        if (t < SS-1) {
            for (int idx = tx; idx < 64*8; idx += 1024) {
                int r = idx>>3, c4 = idx&7;
                cpa16(sptr(&As[((t+1)&1)*2048 + r*32 + ((c4*4) ^ ((r&3)<<3))]),
                      &r_emb[Tk[(t+1)*64+r]*32 + c4*4]);
            }
            CPCOMMIT(); CPWAIT(1);
        } else CPWAIT(0);
        __syncthreads();
        const unsigned* Ab = As + (t&1)*2048;
        const unsigned* Hb = Hs + (t&1)*2048;
        unsigned* Hw = Hs + ((t+1)&1)*2048;
        float acc[4][4];
        #pragma unroll
        for (int g = 0; g < 4; g++) {
            acc[g][0]=bA[g][0]; acc[g][1]=bA[g][1];
            acc[g][2]=bA[g][0]; acc[g][3]=bA[g][1];
        }
        #pragma unroll
        for (int kg = 0; kg < 4; kg++) {
            const int woff = ((kg*4 + tig)<<1) ^ sw;
            unsigned a[4], bf[4][2];
            ldA64(a, Ab, m0+gid, 32, woff);
            #pragma unroll
            for (int g = 0; g < 4; g++) {
                uint2 w = *(const uint2*)&Wi[(g*64 + wn*8 + gid)*32 + woff];
                bf[g][0]=w.x; bf[g][1]=w.y;
            }
            #pragma unroll
            for (int g = 0; g < 4; g++) mma16(acc[g], a, bf[g]);
        }
        #pragma unroll
        for (int kg = 0; kg < 4; kg++) {
            const int woff = ((kg*4 + tig)<<1) ^ sw;
            unsigned a[4], bf[4][2];
            ldA64(a, Hb, m0+gid, 32, woff);
            #pragma unroll
            for (int g = 0; g < 4; g++) {
                uint2 w = *(const uint2*)&Wh[(g*64 + wn*8 + gid)*32 + woff];
                bf[g][0]=w.x; bf[g][1]=w.y;
            }
            #pragma unroll
            for (int g = 0; g < 4; g++) mma16(acc[g], a, bf[g]);
        }
        {
            float hv[4];
            #pragma unroll
            for (int q = 0; q < 4; q++) {
                float iv = asigm(acc[0][q]);
                float fv = asigm(acc[1][q]);
                float gv = atanh_(acc[2][q]);
                float ov = asigm(acc[3][q]);
                float c = fv*creg[q] + iv*gv;
                hv[q] = ov*atanh_(c);
                creg[q] = c;
            }
            unsigned p1 = h2(hv[0], hv[1]);
            unsigned p2 = h2(hv[2], hv[3]);
            int r1 = m0 + gid, r2 = r1 + 8;
            Hw[r1*32 + pj] = p1;
            Hw[r2*32 + pj] = p2;
            H[(size_t)(t*BB + b0 + r1)*32 + pn] = p1;
            H[(size_t)(t*BB + b0 + r2)*32 + pn] = p2;
        }
    }
}

// ======== K3: Gc = [hf|hb] @ Wih_c^T + biases (interleaved out cols, fp32) ====
__global__ __launch_bounds__(256,2) void k3(
    const float* __restrict__ bic, const float* __restrict__ bhc)
{
    extern __shared__ unsigned sm[];
    unsigned* Ab = sm;            // 2 x [128][20]
    unsigned* Bb = sm + 2*2560;   // 2 x [128][20]
    const int tx = threadIdx.x, q = blockIdx.y, r0blk = blockIdx.x*128;
    for (int idx = tx; idx < 512; idx += 256) {
        int r = idx>>2, c4 = idx&3;
        cpa16(sptr(&Ab[r*20 + c4*4]), &g_hf[(size_t)(r0blk+r)*32 + c4*4]);
        cpa16(sptr(&Bb[r*20 + c4*4]), &r_Wc[(q*128+r)*64 + c4*4]);
    }
    CPCOMMIT();
    const int lid = tx&31, wid = tx>>5, gid = lid>>2, tig = lid&3;
    const int wm = wid&1, wn = wid>>1;
    float acc[4][4][4];
    #pragma unroll
    for (int nb = 0; nb < 4; nb++) {
        int col = q*128 + wn*32 + nb*8 + tig*2;
        int o0 = (col&3)*128 + (col>>2);
        int o1 = ((col+1)&3)*128 + ((col+1)>>2);
        float b0v = bic[o0]+bhc[o0], b1v = bic[o1]+bhc[o1];
        #pragma unroll
        for (int mb = 0; mb < 4; mb++) {
            acc[mb][nb][0]=b0v; acc[mb][nb][1]=b1v; acc[mb][nb][2]=b0v; acc[mb][nb][3]=b1v;
        }
    }
    #pragma unroll 1
    for (int c = 0; c < 4; c++) {
        CPWAIT(0); __syncthreads();
        if (c < 3) {
            int cc = c+1, buf = cc&1, koff = (cc&1)*16;
            const unsigned* Asrc = (cc < 2) ? g_hf : g_hb;
            for (int idx = tx; idx < 512; idx += 256) {
                int r = idx>>2, c4 = idx&3;
                cpa16(sptr(&Ab[buf*2560 + r*20 + c4*4]),
                      &Asrc[(size_t)(r0blk+r)*32 + koff + c4*4]);
                cpa16(sptr(&Bb[buf*2560 + r*20 + c4*4]),
                      &r_Wc[(q*128+r)*64 + cc*16 + c4*4]);
            }
            CPCOMMIT();
        }
        const unsigned* Au = Ab + (c&1)*2560;
        const unsigned* Bu = Bb + (c&1)*2560;
        #pragma unroll
        for (int kg = 0; kg < 2; kg++) {
            unsigned a[4][4], b[4][2];
            #pragma unroll
            for (int mb = 0; mb < 4; mb++) ldA(a[mb], Au, wm*64+mb*16, kg*8, 20, gid, tig);
            #pragma unroll
            for (int nb = 0; nb < 4; nb++) ldB(b[nb], Bu, wn*32+nb*8, kg*8, 20, gid, tig);
            #pragma unroll
            for (int mb = 0; mb < 4; mb++)
                #pragma unroll
                for (int nb = 0; nb < 4; nb++) mma16(acc[mb][nb], a[mb], b[nb]);
        }
    }
    #pragma unroll
    for (int mb = 0; mb < 4; mb++)
        #pragma unroll
        for (int nb = 0; nb < 4; nb++) {
            int row = r0blk + wm*64 + mb*16 + gid;
            int col = q*128 + wn*32 + nb*8 + tig*2;
            *(float2*)&g_Gc[(size_t)row*512 + col]     = make_float2(acc[mb][nb][0],acc[mb][nb][1]);
            *(float2*)&g_Gc[(size_t)(row+8)*512 + col] = make_float2(acc[mb][nb][2],acc[mb][nb][3]);
        }
}

// ======== K4C: combiner recurrence, 2-CTA cluster, 1024 thr, fp16 ====
__global__ __launch_bounds__(1024) __cluster_dims__(2,1,1) void k4c(
    const float* __restrict__ h0c, const float* __restrict__ c0c)
{
    extern __shared__ unsigned sm[];
    unsigned* Ws = sm;              // [256][64] remapped rows, perm+swz
    unsigned* Hs = sm + 16384;      // 2 x [64][64]
    const int tx = threadIdx.x;
    unsigned rank; asm("mov.u32 %0, %%cluster_ctarank;" : "=r"(rank));
    const int b0 = (blockIdx.x >> 1) * 64;

    for (int idx = tx; idx < 256*16; idx += 1024) {
        int n = idx>>4, c4 = idx&15;
        int g = ((n>>3)&1)*2 + (n&1);
        int d = (n>>4)*4 + ((n>>1)&3);
        cpa16(sptr(&Ws[n*64 + ((c4*4) ^ ((n&3)<<3))]),
              &r_Whc[(g*128 + (int)rank*64 + d)*64 + c4*4]);
    }
    CPCOMMIT();
    for (int idx = tx; idx < 64*64; idx += 1024) {
        int r = idx>>6, p = idx&63;
        Hs[r*64 + (pcol(p) ^ ((r&3)<<3))] =
            h2(h0c[(b0+r)*128+2*p], h0c[(b0+r)*128+2*p+1]);
    }

    const int lid = tx&31, wid = tx>>5, gid = lid>>2, tig = lid&3;
    const int wm2 = wid>>4;
    const int wcol = wid&15;
    const int n0 = wcol*16;
    const int sw = (gid&3)<<3;
    const int dloc = wcol*4 + tig;
    const int gd = (int)rank*64 + dloc;
    const int pw = pcol(gd>>1) ^ sw;
    unsigned peerHs;
    asm("mapa.shared::cluster.u32 %0, %1, %2;"
        : "=r"(peerHs) : "r"(sptr(Hs)), "r"(rank^1u));

    float creg[2][2];
    #pragma unroll
    for (int mb = 0; mb < 2; mb++) {
        creg[mb][0] = c0c[(b0+wm2*32+mb*16+gid)*128 + gd];
        creg[mb][1] = c0c[(b0+wm2*32+mb*16+gid+8)*128 + gd];
    }
    CPWAIT(0);
    __syncthreads();

    #pragma unroll 1
    for (int t = 0; t < SS; t++) {
        const unsigned* Hb = Hs + (t&1)*4096;
        unsigned* Hw = Hs + ((t+1)&1)*4096;
        const unsigned pbuf = ((unsigned)((t+1)&1))*16384u;
        float4 gq[4];
        #pragma unroll
        for (int mb = 0; mb < 2; mb++) {
            gq[2*mb]   = __ldg((const float4*)&g_Gc[(size_t)(t*BB+b0+wm2*32+mb*16+gid)*512 + 4*gd]);
            gq[2*mb+1] = __ldg((const float4*)&g_Gc[(size_t)(t*BB+b0+wm2*32+mb*16+gid+8)*512 + 4*gd]);
        }
        float acc[2][2][4];
        #pragma unroll
        for (int mb = 0; mb < 2; mb++)
            #pragma unroll
            for (int nb = 0; nb < 2; nb++)
                #pragma unroll
                for (int r = 0; r < 4; r++) acc[mb][nb][r] = 0.f;
        #pragma unroll
        for (int kg = 0; kg < 8; kg++) {
            const int woff = ((kg*4 + tig)<<1) ^ sw;
            unsigned a[2][4], bf[2][2];
            #pragma unroll
            for (int mb = 0; mb < 2; mb++) ldA64(a[mb], Hb, wm2*32+mb*16+gid, 64, woff);
            #pragma unroll
            for (int nb = 0; nb < 2; nb++) {
                uint2 w = *(const uint2*)&Ws[(n0 + nb*8 + gid)*64 + woff];
                bf[nb][0]=w.x; bf[nb][1]=w.y;
            }
            #pragma unroll
            for (int mb = 0; mb < 2; mb++)
                #pragma unroll
                for (int nb = 0; nb < 2; nb++) mma16(acc[mb][nb], a[mb], bf[nb]);
        }
        #pragma unroll
        for (int mb = 0; mb < 2; mb++) {
            float4 q0 = gq[2*mb], q1 = gq[2*mb+1];
            float iv0 = asigm (acc[mb][0][0] + q0.x);
            float fv0 = asigm (acc[mb][0][1] + q0.y);
            float gv0 = atanh_(acc[mb][1][0] + q0.z);
            float ov0 = asigm (acc[mb][1][1] + q0.w);
            float iv1 = asigm (acc[mb][0][2] + q1.x);
            float fv1 = asigm (acc[mb][0][3] + q1.y);
            float gv1 = atanh_(acc[mb][1][2] + q1.z);
            float ov1 = asigm (acc[mb][1][3] + q1.w);
            float cn0 = fv0*creg[mb][0] + iv0*gv0;
            float cn1 = fv1*creg[mb][1] + iv1*gv1;
            creg[mb][0]=cn0; creg[mb][1]=cn1;
            float hv0 = ov0*atanh_(cn0);
            float hv1 = ov1*atanh_(cn1);
            float pp0 = __shfl_xor_sync(0xffffffffu, hv0, 1);
            float pp1 = __shfl_xor_sync(0xffffffffu, hv1, 1);
            if ((tig & 1) == 0) {
                unsigned w0v = h2(hv0, pp0);
                unsigned w1v = h2(hv1, pp1);
                int r0 = wm2*32 + mb*16 + gid, r1 = r0 + 8;
                if (t < SS-1) {
                    Hw[r0*64 + pw] = w0v;
                    Hw[r1*64 + pw] = w1v;
                    asm volatile("st.shared::cluster.b32 [%0], %1;"
                        :: "r"(peerHs + pbuf + (unsigned)(r0*64+pw)*4u), "r"(w0v) : "memory");
                    asm volatile("st.shared::cluster.b32 [%0], %1;"
                        :: "r"(peerHs + pbuf + (unsigned)(r1*64+pw)*4u), "r"(w1v) : "memory");
                } else {
                    g_hL[(b0+r0)*64 + pcol(gd>>1)] = w0v;   // PERMUTED for k5
                    g_hL[(b0+r1)*64 + pcol(gd>>1)] = w1v;
                }
            }
        }
        CLSYNC();
    }
}

// ======== K5: out = hL @ Wd^T + bd. Paired LDS.64 fragments, Wd-resident ====
__global__ __launch_bounds__(256,2) void k5(
    const float* __restrict__ bd, float* __restrict__ out)
{
    extern __shared__ unsigned sm[];
    unsigned* Bs = sm;            // [128][64] perm+swz Wd (resident)
    unsigned* Ab = sm + 8192;     // 2 x [128][32] perm+swz hL k-chunks
    const int tx = threadIdx.x;
    const int v0 = blockIdx.x*128;
    const int mbase = blockIdx.y*1024;
    for (int idx = tx; idx < 128*16; idx += 256) {
        int n = idx>>4, c4 = idx&15;
        cpa16(sptr(&Bs[n*64 + ((c4*4) ^ ((n&3)<<3))]), &r_Wd[(size_t)(v0+n)*64 + c4*4]);
    }
    for (int idx = tx; idx < 128*8; idx += 256) {
        int r = idx>>3, c4 = idx&7;
        cpa16(sptr(&Ab[r*32 + ((c4*4) ^ ((r&3)<<3))]), &g_hL[(mbase+r)*64 + c4*4]);
    }
    CPCOMMIT();
    const int lid = tx&31, wid = tx>>5, gid = lid>>2, tig = lid&3;
    const int wm = wid&1, wn = wid>>1;
    const int sw = (gid&3)<<3;
    #pragma unroll 1
    for (int mt = 0; mt < 8; mt++) {
        float acc[4][4][4];
        #pragma unroll
        for (int mb = 0; mb < 4; mb++)
            #pragma unroll
            for (int nb = 0; nb < 4; nb++)
                #pragma unroll
                for (int r = 0; r < 4; r++) acc[mb][nb][r] = 0.f;
        #pragma unroll 1
        for (int c = 0; c < 2; c++) {           // 2 k-chunks of 32 words (64 elems)
            CPWAIT(0); __syncthreads();
            int i = mt*2 + c;
            if (i < 15) {
                int nm = (i+1)>>1, ncc = (i+1)&1, buf = (i+1)&1;
                for (int idx = tx; idx < 128*8; idx += 256) {
                    int r = idx>>3, c4 = idx&7;
                    cpa16(sptr(&Ab[buf*4096 + r*32 + ((c4*4) ^ ((r&3)<<3))]),
                          &g_hL[(mbase + nm*128 + r)*64 + ncc*32 + c4*4]);
                }
                CPCOMMIT();
            }
            const unsigned* Au = Ab + (i&1)*4096;
            #pragma unroll
            for (int kg = 0; kg < 4; kg++) {
                const int woff  = ((kg*4 + tig)<<1) ^ sw;
                const int woffB = (((c*4+kg)*4 + tig)<<1) ^ sw;
                unsigned a[4][4], b[4][2];
                #pragma unroll
                for (int mb = 0; mb < 4; mb++)
                    ldA64(a[mb], Au, wm*64+mb*16+gid, 32, woff);
                #pragma unroll
                for (int nb = 0; nb < 4; nb++) {
                    uint2 w = *(const uint2*)&Bs[(wn*32+nb*8+gid)*64 + woffB];
                    b[nb][0]=w.x; b[nb][1]=w.y;
                }
                #pragma unroll
                for (int mb = 0; mb < 4; mb++)
                    #pragma unroll
                    for (int nb = 0; nb < 4; nb++) mma16(acc[mb][nb], a[mb], b[nb]);
            }
        }
        #pragma unroll
        for (int mb = 0; mb < 4; mb++)
            #pragma unroll
            for (int nb = 0; nb < 4; nb++) {
                int row = mbase + mt*128 + wm*64 + mb*16 + gid;
                int col = v0 + wn*32 + nb*8 + tig*2;
                float2 bb = *(const float2*)&bd[col];
                stcs2(&out[(size_t)row*VV + col],     acc[mb][nb][0]+bb.x, acc[mb][nb][1]+bb.y);
                stcs2(&out[(size_t)(row+8)*VV + col], acc[mb][nb][2]+bb.x, acc[mb][nb][3]+bb.y);
            }
    }
}

extern "C" void kernel_launch(void* const* d_in, const int* in_sizes, int n_in,
                              void* d_out, int out_size) {
    const void*  x     = d_in[0];
    const float* h0f   = (const float*)d_in[1];
    const float* c0f   = (const float*)d_in[2];
    const float* h0b   = (const float*)d_in[3];
    const float* c0b   = (const float*)d_in[4];
    const float* h0c   = (const float*)d_in[5];
    const float* c0c   = (const float*)d_in[6];
    const float* emb   = (const float*)d_in[7];
    const float* Wih_f = (const float*)d_in[8];
    const float* Whh_f = (const float*)d_in[9];
    const float* bih_f = (const float*)d_in[10];
    const float* bhh_f = (const float*)d_in[11];
    const float* Wih_b = (const float*)d_in[12];
    const float* Whh_b = (const float*)d_in[13];
    const float* bih_b = (const float*)d_in[14];
    const float* bhh_b = (const float*)d_in[15];
    const float* Wih_c = (const float*)d_in[16];
    const float* Whh_c = (const float*)d_in[17];
    const float* bih_c = (const float*)d_in[18];
    const float* bhh_c = (const float*)d_in[19];
    const float* Wd    = (const float*)d_in[20];
    const float* bd    = (const float*)d_in[21];
    float* out = (float*)d_out;

    const int s2  = (24576 + 2048)*4;      // 106496
    const int s3  = (4*2560)*4;            // 40960
    const int s4c = 98304;                 // 96KB
    const int s5  = (8192 + 2*4096)*4;     // 65536
    cudaFuncSetAttribute(k2f, cudaFuncAttributeMaxDynamicSharedMemorySize, s2);
    cudaFuncSetAttribute(k3,  cudaFuncAttributeMaxDynamicSharedMemorySize, s3);
    cudaFuncSetAttribute(k4c, cudaFuncAttributeMaxDynamicSharedMemorySize, s4c);
    cudaFuncSetAttribute(k5,  cudaFuncAttributeMaxDynamicSharedMemorySize, s5);

    k0<<<1024, 256>>>(emb, Wih_f, Whh_f, Wih_b, Whh_b, Wih_c, Whh_c, Wd);
    k2f<<<dim3(BB/64, 2), 1024, s2>>>(x, bih_f, bhh_f, h0f, c0f, bih_b, bhh_b, h0b, c0b);
    k3<<<dim3(SB/128, 4), 256, s3>>>(bih_c, bhh_c);
    k4c<<<128, 1024, s4c>>>(h0c, c0c);
    k5<<<dim3(VV/128, 4), 256, s5>>>(bd, out);
}

// round 17
// speedup vs baseline: 1.3743x; 1.0704x over previous
#include <cuda_runtime.h>
#include <cuda_fp16.h>
#include <math.h>

#define SS 32
#define EE 64
#define VV 32000
#define BB 4096
#define SB (SS*BB)

// packed-fp16 state (word p holds elements 2p,2p+1); g_hL words PERMUTED (pcol)
__device__ unsigned g_hf[(size_t)SB*32];
__device__ unsigned g_hb[(size_t)SB*32];
__device__ float    g_Gc[(size_t)SB*512];   // fp32, GATE-INTERLEAVED cols c = 4*dim+gate
__device__ unsigned g_hL[BB*64];
// packed-fp16 operands; k2f/k4s/k5 arrays word-PERMUTED (pairs (w,w+4) adjacent)
__device__ unsigned r_emb[(size_t)VV*32];
__device__ unsigned r_Wif[256*32], r_Whf[256*32], r_Wib[256*32], r_Whb[256*32];
__device__ unsigned r_Wc[512*64];           // interleaved rows c=4d+g, natural words (k3)
__device__ unsigned r_Whc[512*64];          // original rows, permuted words (k4s)
__device__ unsigned r_Wd[(size_t)VV*64];    // permuted words (k5)

__device__ __forceinline__ float atanh_(float x){
    float r; asm("tanh.approx.f32 %0, %1;" : "=f"(r) : "f"(x)); return r;
}
__device__ __forceinline__ float asigm(float x){ return 0.5f + 0.5f*atanh_(0.5f*x); }
__device__ __forceinline__ unsigned h2(float a, float b){
    __half2 hh = __floats2half2_rn(a, b);
    return *reinterpret_cast<unsigned*>(&hh);
}
__device__ __forceinline__ int pcol(int c){
    int o = c&7; return (c&~7) + ((o<4)? o*2 : (o-4)*2+1);
}
__device__ __forceinline__ unsigned sptr(const void* p){
    return (unsigned)__cvta_generic_to_shared(p);
}
__device__ __forceinline__ void cpa16(unsigned d, const void* s){
    asm volatile("cp.async.cg.shared.global [%0], [%1], 16;" :: "r"(d), "l"(s));
}
#define CPCOMMIT() asm volatile("cp.async.commit_group;")
#define CPWAIT(n)  asm volatile("cp.async.wait_group %0;" :: "n"(n))

__device__ __forceinline__ void mma16(float* c, const unsigned* a, const unsigned* b){
    asm volatile("mma.sync.aligned.m16n8k16.row.col.f32.f16.f16.f32 "
        "{%0,%1,%2,%3}, {%4,%5,%6,%7}, {%8,%9}, {%0,%1,%2,%3};"
        : "+f"(c[0]), "+f"(c[1]), "+f"(c[2]), "+f"(c[3])
        : "r"(a[0]), "r"(a[1]), "r"(a[2]), "r"(a[3]), "r"(b[0]), "r"(b[1]));
}
__device__ __forceinline__ void ldA64(unsigned* a, const unsigned* S, int r0,
                                      int K, int woff){
    uint2 v0 = *(const uint2*)&S[r0*K + woff];
    uint2 v1 = *(const uint2*)&S[(r0+8)*K + woff];
    a[0]=v0.x; a[1]=v1.x; a[2]=v0.y; a[3]=v1.y;
}
__device__ __forceinline__ void ldA(unsigned* a, const unsigned* S, int m0, int k0,
                                    int pad, int gid, int tig){
    a[0] = S[(m0+gid  )*pad + k0+tig  ];
    a[1] = S[(m0+gid+8)*pad + k0+tig  ];
    a[2] = S[(m0+gid  )*pad + k0+tig+4];
    a[3] = S[(m0+gid+8)*pad + k0+tig+4];
}
__device__ __forceinline__ void ldB(unsigned* b, const unsigned* S, int n0, int k0,
                                    int pad, int gid, int tig){
    b[0] = S[(n0+gid)*pad + k0+tig  ];
    b[1] = S[(n0+gid)*pad + k0+tig+4];
}
__device__ __forceinline__ void stcs2(float* p, float x, float y){
    asm volatile("st.global.cs.v2.f32 [%0], {%1,%2};" :: "l"(p), "f"(x), "f"(y) : "memory");
}

// ======== K0 ========
__global__ void k0(const float* __restrict__ emb,
    const float* __restrict__ Wif, const float* __restrict__ Whf,
    const float* __restrict__ Wib, const float* __restrict__ Whb,
    const float* __restrict__ Wc,  const float* __restrict__ Whc,
    const float* __restrict__ Wd)
{
    int tid = blockIdx.x*256 + threadIdx.x, nt = gridDim.x*256;
    for (int i = tid; i < VV*32; i += nt) {
        int v = i>>5, p = i&31;
        r_emb[v*32 + pcol(p)] = h2(emb[v*64+2*p], emb[v*64+2*p+1]);
    }
    for (int i = tid; i < 256*32; i += nt) {
        int n = i>>5, p = i&31, d = n*32 + pcol(p);
        r_Wif[d] = h2(Wif[n*64+2*p], Wif[n*64+2*p+1]);
        r_Whf[d] = h2(Whf[n*64+2*p], Whf[n*64+2*p+1]);
        r_Wib[d] = h2(Wib[n*64+2*p], Wib[n*64+2*p+1]);
        r_Whb[d] = h2(Whb[n*64+2*p], Whb[n*64+2*p+1]);
    }
    for (int i = tid; i < 512*64; i += nt) {
        int n = i>>6, p = i&63;
        int g = n>>7, dd = n&127;
        r_Wc[(dd*4+g)*64 + p] = h2(Wc[n*128+2*p], Wc[n*128+2*p+1]);     // k3
        r_Whc[n*64 + pcol(p)] = h2(Whc[n*128+2*p], Whc[n*128+2*p+1]);   // k4s
    }
    for (int i = tid; i < VV*64; i += nt) {
        int n = i>>6, p = i&63;
        r_Wd[n*64 + pcol(p)] = h2(Wd[(size_t)n*128+2*p], Wd[(size_t)n*128+2*p+1]);
    }
}

// ======== K2F: fused embed+gates+recurrence. 64 rows/CTA, 1024 thr, grid 128 ====
__global__ __launch_bounds__(1024) void k2f(const void* __restrict__ xraw,
    const float* __restrict__ bif, const float* __restrict__ bhf,
    const float* __restrict__ h0f, const float* __restrict__ c0f,
    const float* __restrict__ bib, const float* __restrict__ bhb,
    const float* __restrict__ h0b, const float* __restrict__ c0b)
{
    extern __shared__ unsigned sm[];
    unsigned* Wi = sm;              // [256][32] perm+swz
    unsigned* Wh = sm + 8192;       // [256][32]
    unsigned* As = sm + 16384;      // 2 x [64][32]
    unsigned* Hs = sm + 20480;      // 2 x [64][32]
    int*      Tk = (int*)(sm + 24576);
    __shared__ int s64;
    const int tx = threadIdx.x, dir = blockIdx.y, b0 = blockIdx.x*64;
    const unsigned* Wih = dir ? r_Wib : r_Wif;
    const unsigned* Whh = dir ? r_Whb : r_Whf;
    const float* bi  = dir ? bib : bif;
    const float* bh  = dir ? bhb : bhf;
    const float* h0  = dir ? h0b : h0f;
    const float* c0  = dir ? c0b : c0f;
    unsigned* H = dir ? g_hb : g_hf;

    for (int idx = tx; idx < 256*8; idx += 1024) {
        int n = idx>>3, c4 = idx&7;
        int dst = n*32 + ((c4*4) ^ ((n&3)<<3));
        cpa16(sptr(&Wi[dst]), &Wih[n*32 + c4*4]);
        cpa16(sptr(&Wh[dst]), &Whh[n*32 + c4*4]);
    }
    CPCOMMIT();
    if (tx == 0) {
        const int* p = (const int*)xraw; int f = 1;
        for (int q = 0; q < 64; q++) if (p[2*q+1] != 0) { f = 0; break; }
        s64 = f;
    }
    __syncthreads();
    {
        const long long* x64 = (const long long*)xraw;
        const int* x32 = (const int*)xraw;
        const int is64 = s64;
        for (int idx = tx; idx < 2048; idx += 1024) {
            int t = idx>>6, r = idx&63;
            int pos = dir ? (SS-1-t)*BB + b0 + r : t*BB + b0 + r;
            Tk[idx] = is64 ? (int)x64[pos] : x32[pos];
        }
    }
    for (int idx = tx; idx < 64*32; idx += 1024) {
        int r = idx>>5, p = idx&31;
        Hs[r*32 + (pcol(p) ^ ((r&3)<<3))] =
            h2(h0[(b0+r)*64+2*p], h0[(b0+r)*64+2*p+1]);
    }
    __syncthreads();
    for (int idx = tx; idx < 64*8; idx += 1024) {
        int r = idx>>3, c4 = idx&7;
        cpa16(sptr(&As[r*32 + ((c4*4) ^ ((r&3)<<3))]), &r_emb[Tk[r]*32 + c4*4]);
    }
    CPCOMMIT();

    const int lid = tx&31, wid = tx>>5, gid = lid>>2, tig = lid&3;
    const int wm = wid>>3, wn = wid&7;
    const int m0 = wm*16;
    const int jc = wn*8 + tig*2;
    const int sw = (gid&3)<<3;
    float bA[4][2];
    #pragma unroll
    for (int g = 0; g < 4; g++) {
        bA[g][0] = bi[g*64+jc]   + bh[g*64+jc];
        bA[g][1] = bi[g*64+jc+1] + bh[g*64+jc+1];
    }
    float creg[4];
    {
        float2 c1 = *(const float2*)&c0[(b0+m0+gid)*64 + jc];
        float2 c2 = *(const float2*)&c0[(b0+m0+gid+8)*64 + jc];
        creg[0]=c1.x; creg[1]=c1.y; creg[2]=c2.x; creg[3]=c2.y;
    }
    const int pj = pcol(jc>>1) ^ sw;
    const int pn = jc>>1;
    for (int t = 0; t < SS; t++) {
        if (t < SS-1) {
            for (int idx = tx; idx < 64*8; idx += 1024) {
                int r = idx>>3, c4 = idx&7;
                cpa16(sptr(&As[((t+1)&1)*2048 + r*32 + ((c4*4) ^ ((r&3)<<3))]),
                      &r_emb[Tk[(t+1)*64+r]*32 + c4*4]);
            }
            CPCOMMIT(); CPWAIT(1);
        } else CPWAIT(0);
        __syncthreads();
        const unsigned* Ab = As + (t&1)*2048;
        const unsigned* Hb = Hs + (t&1)*2048;
        unsigned* Hw = Hs + ((t+1)&1)*2048;
        float acc[4][4];
        #pragma unroll
        for (int g = 0; g < 4; g++) {
            acc[g][0]=bA[g][0]; acc[g][1]=bA[g][1];
            acc[g][2]=bA[g][0]; acc[g][3]=bA[g][1];
        }
        #pragma unroll
        for (int kg = 0; kg < 4; kg++) {
            const int woff = ((kg*4 + tig)<<1) ^ sw;
            unsigned a[4], bf[4][2];
            ldA64(a, Ab, m0+gid, 32, woff);
            #pragma unroll
            for (int g = 0; g < 4; g++) {
                uint2 w = *(const uint2*)&Wi[(g*64 + wn*8 + gid)*32 + woff];
                bf[g][0]=w.x; bf[g][1]=w.y;
            }
            #pragma unroll
            for (int g = 0; g < 4; g++) mma16(acc[g], a, bf[g]);
        }
        #pragma unroll
        for (int kg = 0; kg < 4; kg++) {
            const int woff = ((kg*4 + tig)<<1) ^ sw;
            unsigned a[4], bf[4][2];
            ldA64(a, Hb, m0+gid, 32, woff);
            #pragma unroll
            for (int g = 0; g < 4; g++) {
                uint2 w = *(const uint2*)&Wh[(g*64 + wn*8 + gid)*32 + woff];
                bf[g][0]=w.x; bf[g][1]=w.y;
            }
            #pragma unroll
            for (int g = 0; g < 4; g++) mma16(acc[g], a, bf[g]);
        }
        {
            float hv[4];
            #pragma unroll
            for (int q = 0; q < 4; q++) {
                float iv = asigm(acc[0][q]);
                float fv = asigm(acc[1][q]);
                float gv = atanh_(acc[2][q]);
                float ov = asigm(acc[3][q]);
                float c = fv*creg[q] + iv*gv;
                hv[q] = ov*atanh_(c);
                creg[q] = c;
            }
            unsigned p1 = h2(hv[0], hv[1]);
            unsigned p2 = h2(hv[2], hv[3]);
            int r1 = m0 + gid, r2 = r1 + 8;
            Hw[r1*32 + pj] = p1;
            Hw[r2*32 + pj] = p2;
            H[(size_t)(t*BB + b0 + r1)*32 + pn] = p1;
            H[(size_t)(t*BB + b0 + r2)*32 + pn] = p2;
        }
    }
}

// ======== K3: Gc = [hf|hb] @ Wih_c^T + biases (interleaved out cols, fp32) ====
__global__ __launch_bounds__(256,2) void k3(
    const float* __restrict__ bic, const float* __restrict__ bhc)
{
    extern __shared__ unsigned sm[];
    unsigned* Ab = sm;            // 2 x [128][20]
    unsigned* Bb = sm + 2*2560;   // 2 x [128][20]
    const int tx = threadIdx.x, q = blockIdx.y, r0blk = blockIdx.x*128;
    for (int idx = tx; idx < 512; idx += 256) {
        int r = idx>>2, c4 = idx&3;
        cpa16(sptr(&Ab[r*20 + c4*4]), &g_hf[(size_t)(r0blk+r)*32 + c4*4]);
        cpa16(sptr(&Bb[r*20 + c4*4]), &r_Wc[(q*128+r)*64 + c4*4]);
    }
    CPCOMMIT();
    const int lid = tx&31, wid = tx>>5, gid = lid>>2, tig = lid&3;
    const int wm = wid&1, wn = wid>>1;
    float acc[4][4][4];
    #pragma unroll
    for (int nb = 0; nb < 4; nb++) {
        int col = q*128 + wn*32 + nb*8 + tig*2;
        int o0 = (col&3)*128 + (col>>2);
        int o1 = ((col+1)&3)*128 + ((col+1)>>2);
        float b0v = bic[o0]+bhc[o0], b1v = bic[o1]+bhc[o1];
        #pragma unroll
        for (int mb = 0; mb < 4; mb++) {
            acc[mb][nb][0]=b0v; acc[mb][nb][1]=b1v; acc[mb][nb][2]=b0v; acc[mb][nb][3]=b1v;
        }
    }
    #pragma unroll 1
    for (int c = 0; c < 4; c++) {
        CPWAIT(0); __syncthreads();
        if (c < 3) {
            int cc = c+1, buf = cc&1, koff = (cc&1)*16;
            const unsigned* Asrc = (cc < 2) ? g_hf : g_hb;
            for (int idx = tx; idx < 512; idx += 256) {
                int r = idx>>2, c4 = idx&3;
                cpa16(sptr(&Ab[buf*2560 + r*20 + c4*4]),
                      &Asrc[(size_t)(r0blk+r)*32 + koff + c4*4]);
                cpa16(sptr(&Bb[buf*2560 + r*20 + c4*4]),
                      &r_Wc[(q*128+r)*64 + cc*16 + c4*4]);
            }
            CPCOMMIT();
        }
        const unsigned* Au = Ab + (c&1)*2560;
        const unsigned* Bu = Bb + (c&1)*2560;
        #pragma unroll
        for (int kg = 0; kg < 2; kg++) {
            unsigned a[4][4], b[4][2];
            #pragma unroll
            for (int mb = 0; mb < 4; mb++) ldA(a[mb], Au, wm*64+mb*16, kg*8, 20, gid, tig);
            #pragma unroll
            for (int nb = 0; nb < 4; nb++) ldB(b[nb], Bu, wn*32+nb*8, kg*8, 20, gid, tig);
            #pragma unroll
            for (int mb = 0; mb < 4; mb++)
                #pragma unroll
                for (int nb = 0; nb < 4; nb++) mma16(acc[mb][nb], a[mb], b[nb]);
        }
    }
    #pragma unroll
    for (int mb = 0; mb < 4; mb++)
        #pragma unroll
        for (int nb = 0; nb < 4; nb++) {
            int row = r0blk + wm*64 + mb*16 + gid;
            int col = q*128 + wn*32 + nb*8 + tig*2;
            *(float2*)&g_Gc[(size_t)row*512 + col]     = make_float2(acc[mb][nb][0],acc[mb][nb][1]);
            *(float2*)&g_Gc[(size_t)(row+8)*512 + col] = make_float2(acc[mb][nb][2],acc[mb][nb][3]);
        }
}

// ======== K4S: combiner recurrence, SINGLE CTA owns all 128 dims, no cluster ====
// 128 CTAs x 1024 thr, 32 batch rows/CTA. Whh_c fully resident (128 KB fp16).
// Ws row n = wid*16 + nb*8 + tig*2 + e  <->  (gate = nb*2+e, dim = wid*4+tig).
__global__ __launch_bounds__(1024) void k4s(
    const float* __restrict__ h0c, const float* __restrict__ c0c)
{
    extern __shared__ unsigned sm[];
    unsigned* Ws = sm;              // [512][64] remapped rows, perm+swz (128 KB)
    unsigned* Hs = sm + 32768;      // 2 x [32][64] (16 KB)
    const int tx = threadIdx.x;
    const int b0 = blockIdx.x * 32;

    for (int idx = tx; idx < 512*16; idx += 1024) {
        int n = idx>>4, c4 = idx&15;
        int g = ((n>>3)&1)*2 + (n&1);
        int d = (n>>4)*4 + ((n>>1)&3);
        cpa16(sptr(&Ws[n*64 + ((c4*4) ^ ((n&3)<<3))]),
              &r_Whc[(g*128 + d)*64 + c4*4]);
    }
    CPCOMMIT();
    for (int idx = tx; idx < 32*64; idx += 1024) {
        int r = idx>>6, p = idx&63;
        Hs[r*64 + (pcol(p) ^ ((r&3)<<3))] =
            h2(h0c[(b0+r)*128+2*p], h0c[(b0+r)*128+2*p+1]);
    }

    const int lid = tx&31, wid = tx>>5, gid = lid>>2, tig = lid&3;
    const int n0 = wid*16;
    const int sw = (gid&3)<<3;
    const int gd = wid*4 + tig;           // hidden dim 0..127
    const int pw = pcol(gd>>1) ^ sw;
    const int pg = pcol(gd>>1);

    float creg[2][2];
    #pragma unroll
    for (int mb = 0; mb < 2; mb++) {
        creg[mb][0] = c0c[(b0+mb*16+gid)*128 + gd];
        creg[mb][1] = c0c[(b0+mb*16+gid+8)*128 + gd];
    }
    CPWAIT(0);
    __syncthreads();

    #pragma unroll 1
    for (int t = 0; t < SS; t++) {
        const unsigned* Hb = Hs + (t&1)*2048;
        unsigned* Hw = Hs + ((t+1)&1)*2048;
        float4 gq[4];
        #pragma unroll
        for (int mb = 0; mb < 2; mb++) {
            gq[2*mb]   = __ldg((const float4*)&g_Gc[(size_t)(t*BB+b0+mb*16+gid)*512 + 4*gd]);
            gq[2*mb+1] = __ldg((const float4*)&g_Gc[(size_t)(t*BB+b0+mb*16+gid+8)*512 + 4*gd]);
        }
        float acc[2][2][4];
        #pragma unroll
        for (int mb = 0; mb < 2; mb++)
            #pragma unroll
            for (int nb = 0; nb < 2; nb++)
                #pragma unroll
                for (int r = 0; r < 4; r++) acc[mb][nb][r] = 0.f;
        #pragma unroll
        for (int kg = 0; kg < 8; kg++) {
            const int woff = ((kg*4 + tig)<<1) ^ sw;
            unsigned a[2][4], bf[2][2];
            #pragma unroll
            for (int mb = 0; mb < 2; mb++) ldA64(a[mb], Hb, mb*16+gid, 64, woff);
            #pragma unroll
            for (int nb = 0; nb < 2; nb++) {
                uint2 w = *(const uint2*)&Ws[(n0 + nb*8 + gid)*64 + woff];
                bf[nb][0]=w.x; bf[nb][1]=w.y;
            }
            #pragma unroll
            for (int mb = 0; mb < 2; mb++)
                #pragma unroll
                for (int nb = 0; nb < 2; nb++) mma16(acc[mb][nb], a[mb], bf[nb]);
        }
        #pragma unroll
        for (int mb = 0; mb < 2; mb++) {
            float4 q0 = gq[2*mb], q1 = gq[2*mb+1];
            float iv0 = asigm (acc[mb][0][0] + q0.x);
            float fv0 = asigm (acc[mb][0][1] + q0.y);
            float gv0 = atanh_(acc[mb][1][0] + q0.z);
            float ov0 = asigm (acc[mb][1][1] + q0.w);
            float iv1 = asigm (acc[mb][0][2] + q1.x);
            float fv1 = asigm (acc[mb][0][3] + q1.y);
            float gv1 = atanh_(acc[mb][1][2] + q1.z);
            float ov1 = asigm (acc[mb][1][3] + q1.w);
            float cn0 = fv0*creg[mb][0] + iv0*gv0;
            float cn1 = fv1*creg[mb][1] + iv1*gv1;
            creg[mb][0]=cn0; creg[mb][1]=cn1;
            float hv0 = ov0*atanh_(cn0);
            float hv1 = ov1*atanh_(cn1);
            float pp0 = __shfl_xor_sync(0xffffffffu, hv0, 1);
            float pp1 = __shfl_xor_sync(0xffffffffu, hv1, 1);
            if ((tig & 1) == 0) {
                unsigned w0v = h2(hv0, pp0);
                unsigned w1v = h2(hv1, pp1);
                int r0 = mb*16 + gid, r1 = r0 + 8;
                if (t < SS-1) {
                    Hw[r0*64 + pw] = w0v;
                    Hw[r1*64 + pw] = w1v;
                } else {
                    g_hL[(b0+r0)*64 + pg] = w0v;
                    g_hL[(b0+r1)*64 + pg] = w1v;
                }
            }
        }
        __syncthreads();
    }
}

// ======== K5: out = hL @ Wd^T + bd. 3 CTAs/SM, 64x128 tile, full-K chunks ====
__global__ __launch_bounds__(256,3) void k5(
    const float* __restrict__ bd, float* __restrict__ out)
{
    extern __shared__ unsigned sm[];
    unsigned* Bs = sm;            // [128][64] perm+swz Wd (resident, 32 KB)
    unsigned* Ab = sm + 8192;     // 2 x [64][64] perm+swz hL m-tiles (32 KB)
    const int tx = threadIdx.x;
    const int v0 = blockIdx.x*128;
    const int mbase = blockIdx.y*1024;
    for (int idx = tx; idx < 128*16; idx += 256) {
        int n = idx>>4, c4 = idx&15;
        cpa16(sptr(&Bs[n*64 + ((c4*4) ^ ((n&3)<<3))]), &r_Wd[(size_t)(v0+n)*64 + c4*4]);
    }
    for (int idx = tx; idx < 64*16; idx += 256) {
        int r = idx>>4, c4 = idx&15;
        cpa16(sptr(&Ab[r*64 + ((c4*4) ^ ((r&3)<<3))]), &g_hL[(mbase+r)*64 + c4*4]);
    }
    CPCOMMIT();
    const int lid = tx&31, wid = tx>>5, gid = lid>>2, tig = lid&3;
    const int wm = wid&1, wn = wid>>1;
    const int sw = (gid&3)<<3;
    #pragma unroll 1
    for (int mt = 0; mt < 16; mt++) {
        CPWAIT(0); __syncthreads();
        if (mt < 15) {
            int buf = (mt+1)&1;
            for (int idx = tx; idx < 64*16; idx += 256) {
                int r = idx>>4, c4 = idx&15;
                cpa16(sptr(&Ab[buf*4096 + r*64 + ((c4*4) ^ ((r&3)<<3))]),
                      &g_hL[(mbase + (mt+1)*64 + r)*64 + c4*4]);
            }
            CPCOMMIT();
        }
        const unsigned* Au = Ab + (mt&1)*4096;
        float acc[2][4][4];
        #pragma unroll
        for (int mb = 0; mb < 2; mb++)
            #pragma unroll
            for (int nb = 0; nb < 4; nb++)
                #pragma unroll
                for (int r = 0; r < 4; r++) acc[mb][nb][r] = 0.f;
        #pragma unroll
        for (int kg = 0; kg < 8; kg++) {
            const int woff = ((kg*4 + tig)<<1) ^ sw;
            unsigned a[2][4], b[4][2];
            #pragma unroll
            for (int mb = 0; mb < 2; mb++)
                ldA64(a[mb], Au, wm*32+mb*16+gid, 64, woff);
            #pragma unroll
            for (int nb = 0; nb < 4; nb++) {
                uint2 w = *(const uint2*)&Bs[(wn*32+nb*8+gid)*64 + woff];
                b[nb][0]=w.x; b[nb][1]=w.y;
            }
            #pragma unroll
            for (int mb = 0; mb < 2; mb++)
                #pragma unroll
                for (int nb = 0; nb < 4; nb++) mma16(acc[mb][nb], a[mb], b[nb]);
        }
        #pragma unroll
        for (int mb = 0; mb < 2; mb++)
            #pragma unroll
            for (int nb = 0; nb < 4; nb++) {
                int row = mbase + mt*64 + wm*32 + mb*16 + gid;
                int col = v0 + wn*32 + nb*8 + tig*2;
                float2 bb = *(const float2*)&bd[col];
                stcs2(&out[(size_t)row*VV + col],     acc[mb][nb][0]+bb.x, acc[mb][nb][1]+bb.y);
                stcs2(&out[(size_t)(row+8)*VV + col], acc[mb][nb][2]+bb.x, acc[mb][nb][3]+bb.y);
            }
    }
}

extern "C" void kernel_launch(void* const* d_in, const int* in_sizes, int n_in,
                              void* d_out, int out_size) {
    const void*  x     = d_in[0];
    const float* h0f   = (const float*)d_in[1];
    const float* c0f   = (const float*)d_in[2];
    const float* h0b   = (const float*)d_in[3];
    const float* c0b   = (const float*)d_in[4];
    const float* h0c   = (const float*)d_in[5];
    const float* c0c   = (const float*)d_in[6];
    const float* emb   = (const float*)d_in[7];
    const float* Wih_f = (const float*)d_in[8];
    const float* Whh_f = (const float*)d_in[9];
    const float* bih_f = (const float*)d_in[10];
    const float* bhh_f = (const float*)d_in[11];
    const float* Wih_b = (const float*)d_in[12];
    const float* Whh_b = (const float*)d_in[13];
    const float* bih_b = (const float*)d_in[14];
    const float* bhh_b = (const float*)d_in[15];
    const float* Wih_c = (const float*)d_in[16];
    const float* Whh_c = (const float*)d_in[17];
    const float* bih_c = (const float*)d_in[18];
    const float* bhh_c = (const float*)d_in[19];
    const float* Wd    = (const float*)d_in[20];
    const float* bd    = (const float*)d_in[21];
    float* out = (float*)d_out;

    const int s2  = (24576 + 2048)*4;      // 106496
    const int s3  = (4*2560)*4;            // 40960
    const int s4s = (32768 + 4096)*4;      // 147456
    const int s5  = (8192 + 2*4096)*4;     // 65536
    cudaFuncSetAttribute(k2f, cudaFuncAttributeMaxDynamicSharedMemorySize, s2);
    cudaFuncSetAttribute(k3,  cudaFuncAttributeMaxDynamicSharedMemorySize, s3);
    cudaFuncSetAttribute(k4s, cudaFuncAttributeMaxDynamicSharedMemorySize, s4s);
    cudaFuncSetAttribute(k5,  cudaFuncAttributeMaxDynamicSharedMemorySize, s5);

    k0<<<1024, 256>>>(emb, Wih_f, Whh_f, Wih_b, Whh_b, Wih_c, Whh_c, Wd);
    k2f<<<dim3(BB/64, 2), 1024, s2>>>(x, bih_f, bhh_f, h0f, c0f, bih_b, bhh_b, h0b, c0b);
    k3<<<dim3(SB/128, 4), 256, s3>>>(bih_c, bhh_c);
    k4s<<<BB/32, 1024, s4s>>>(h0c, c0c);
    k5<<<dim3(VV/128, 4), 256, s5>>>(bd, out);
}